// round 3
// baseline (speedup 1.0000x reference)
#include <cuda_runtime.h>
#include <cuda_fp16.h>

#define BQ 16
#define NN 2048
#define DD 64
#define INV_SQRT 0.022097086912079608f   // 1/sqrt(2048)
#define NEG_FILL -1000.0f

// Scratch: P^T (exp'd masked scores, transposed: [b][m][n]) + reciprocal denominators.
__device__ __half g_PT[(size_t)BQ * NN * NN];   // 134 MB
__device__ float  g_rdenom[BQ * NN];

// ---------------- Kernel 1: scores + exp + column sums + P^T store ----------------
// Block: (m-tile of 128, batch b). 256 threads, 8x8 register tile over (n x m).
// smem layout (bytes):
#define K1_KT 0                      // float Kt[64][128]  (transposed+swizzled)  32768
#define K1_QT 32768                  // float Qt[64][128]                         32768
#define K1_PS 65536                  // __half Ps[64][136]                        17408
#define K1_MS (65536 + 17408)        // uint  Ms[128][33]                         16896
#define K1_SMEM (K1_MS + 16896)      // 99840

__global__ void __launch_bounds__(256, 2)
attn_k1(const float* __restrict__ q, const float* __restrict__ k,
        const int* __restrict__ mask)
{
    extern __shared__ char sm[];
    float*        Kt  = (float*)(sm + K1_KT);
    float*        Qt  = (float*)(sm + K1_QT);
    float4*       Kt4 = (float4*)Kt;
    float4*       Qt4 = (float4*)Qt;
    __half*       Ps  = (__half*)(sm + K1_PS);
    unsigned int* Ms  = (unsigned int*)(sm + K1_MS);
    float*        red = (float*)(sm + K1_PS);   // reused after main loop (8704B <= 17408B)

    const int t  = threadIdx.x;
    const int tx = t & 15;        // n direction
    const int ty = t >> 4;        // m direction
    const int mt = blockIdx.x;
    const int b  = blockIdx.y;
    const int m0 = mt * 128;

    // Load K tile [128 m][64 d] -> Kt[d][m], XOR-swizzled (phys4 = (m>>2) ^ (d&31))
    {
        const float4* kg = (const float4*)(k + ((size_t)b * NN + m0) * DD);
        #pragma unroll
        for (int i = 0; i < 8; i++) {
            int f = t + i * 256;
            int m = f >> 4, dg = f & 15;
            float4 val = kg[f];
            float vv[4] = {val.x, val.y, val.z, val.w};
            #pragma unroll
            for (int j = 0; j < 4; j++) {
                int d  = dg * 4 + j;
                int p4 = (m >> 2) ^ (d & 31);
                Kt[d * 128 + p4 * 4 + (m & 3)] = vv[j];
            }
        }
    }

    float msum[8];
    #pragma unroll
    for (int j = 0; j < 8; j++) msum[j] = 0.f;

    for (int nc = 0; nc < 16; nc++) {
        const int n0 = nc * 128;
        __syncthreads();

        // Load Q chunk [128 n][64 d] -> Qt[d][n], same swizzle
        {
            const float4* qg = (const float4*)(q + ((size_t)b * NN + n0) * DD);
            #pragma unroll
            for (int i = 0; i < 8; i++) {
                int f = t + i * 256;
                int n = f >> 4, dg = f & 15;
                float4 val = qg[f];
                float vv[4] = {val.x, val.y, val.z, val.w};
                #pragma unroll
                for (int j = 0; j < 4; j++) {
                    int d  = dg * 4 + j;
                    int p4 = (n >> 2) ^ (d & 31);
                    Qt[d * 128 + p4 * 4 + (n & 3)] = vv[j];
                }
            }
        }
        // Load mask tile (int32 0/1): 128 n-rows x 128 m-ints.
        // Each task: int4 load of 4 consecutive m-values -> pack one flag byte each
        // into a uint word, so downstream byte-tests are unchanged. Coalesced.
        {
            const int* mg = mask + ((size_t)(b * NN + n0)) * NN + m0;
            #pragma unroll
            for (int i = 0; i < 16; i++) {
                int u = t + i * 256;
                int n = u >> 5, c = u & 31;
                int4 mv = *(const int4*)(mg + (size_t)n * NN + c * 4);
                unsigned w = (mv.x ? 0x1u : 0u) | (mv.y ? 0x100u : 0u) |
                             (mv.z ? 0x10000u : 0u) | (mv.w ? 0x1000000u : 0u);
                Ms[n * 33 + c] = w;
            }
        }
        __syncthreads();

        // 128x128 tile: acc[ii][jj], ii over n, jj over m
        float acc[8][8];
        #pragma unroll
        for (int ii = 0; ii < 8; ii++)
            #pragma unroll
            for (int jj = 0; jj < 8; jj++) acc[ii][jj] = 0.f;

        #pragma unroll 8
        for (int d = 0; d < 64; d++) {
            int x = d & 31;
            float4 a0 = Qt4[d * 32 + (tx ^ x)];
            float4 a1 = Qt4[d * 32 + ((tx + 16) ^ x)];
            float4 b0 = Kt4[d * 32 + (ty ^ x)];
            float4 b1 = Kt4[d * 32 + ((ty + 16) ^ x)];
            float a[8] = {a0.x, a0.y, a0.z, a0.w, a1.x, a1.y, a1.z, a1.w};
            float bb[8] = {b0.x, b0.y, b0.z, b0.w, b1.x, b1.y, b1.z, b1.w};
            #pragma unroll
            for (int ii = 0; ii < 8; ii++)
                #pragma unroll
                for (int jj = 0; jj < 8; jj++)
                    acc[ii][jj] += a[ii] * bb[jj];
        }

        // mask -> -1000, scale, exp; accumulate column sums
        #pragma unroll
        for (int ii = 0; ii < 8; ii++) {
            int n = (ii < 4) ? (tx * 4 + ii) : (64 + tx * 4 + (ii - 4));
            unsigned wA = Ms[n * 33 + ty];
            unsigned wB = Ms[n * 33 + 16 + ty];
            #pragma unroll
            for (int j = 0; j < 4; j++) {
                float sA = ((wA >> (8 * j)) & 255u) ? NEG_FILL : acc[ii][j] * INV_SQRT;
                float eA = __expf(sA);
                msum[j] += eA;
                acc[ii][j] = eA;
                float sB = ((wB >> (8 * j)) & 255u) ? NEG_FILL : acc[ii][4 + j] * INV_SQRT;
                float eB = __expf(sB);
                msum[4 + j] += eB;
                acc[ii][4 + j] = eB;
            }
        }

        // Stage and write P^T, one 64-m half at a time (keeps smem small)
        #pragma unroll
        for (int g = 0; g < 2; g++) {
            __syncthreads();
            #pragma unroll
            for (int i = 0; i < 4; i++) {
                int mrow = ty * 4 + i;
                #pragma unroll
                for (int ii = 0; ii < 8; ii++) {
                    int n = (ii < 4) ? (tx * 4 + ii) : (64 + tx * 4 + (ii - 4));
                    Ps[mrow * 136 + n] = __float2half_rn(acc[ii][g * 4 + i]);
                }
            }
            __syncthreads();
            __half* dst = g_PT + ((size_t)b * NN + m0 + g * 64) * NN + n0;
            #pragma unroll
            for (int i = 0; i < 4; i++) {
                int u = t + i * 256;
                int r = u >> 4, c = u & 15;
                *(uint4*)(dst + (size_t)r * NN + c * 8) = *(uint4*)(Ps + r * 136 + c * 8);
            }
        }
    }

    // Reduce column sums across the 16 tx-threads sharing each m
    __syncthreads();
    #pragma unroll
    for (int j = 0; j < 8; j++) {
        int mrow = (j < 4) ? (ty * 4 + j) : (64 + ty * 4 + (j - 4));
        red[mrow * 17 + tx] = msum[j];
    }
    __syncthreads();
    if (t < 128) {
        float s = 0.f;
        #pragma unroll
        for (int i = 0; i < 16; i++) s += red[t * 17 + i];
        g_rdenom[b * NN + m0 + t] = 1.0f / s;
    }
}

// ---------------- Kernel 2: out = P @ (V * rdenom) ----------------
// Block: (n-tile of 128, batch b). 256 threads. acc 8(n) x 4(d).
#define K2_PT 0                       // float Pt[64][132] = 33792
#define K2_VS 33792                   // float Vs[64][68]  = 17408
#define K2_SMEM (33792 + 17408)       // 51200

__global__ void __launch_bounds__(256)
attn_k2(const float* __restrict__ v, float* __restrict__ out)
{
    extern __shared__ char sm[];
    float* Pt = (float*)(sm + K2_PT);
    float* Vs = (float*)(sm + K2_VS);

    const int t  = threadIdx.x;
    const int tx = t & 15;    // n direction
    const int ty = t >> 4;    // d direction (ty*4 .. ty*4+3)
    const int nt = blockIdx.x;
    const int b  = blockIdx.y;
    const int n0 = nt * 128;

    float acc[8][4];
    #pragma unroll
    for (int ii = 0; ii < 8; ii++)
        #pragma unroll
        for (int j = 0; j < 4; j++) acc[ii][j] = 0.f;

    for (int mc = 0; mc < 32; mc++) {
        const int m0 = mc * 64;
        __syncthreads();
        // Load P^T chunk [64 m][128 n] fp16 -> fp32 smem (natural layout, coalesced)
        // FIXED: 1024 tasks (i<4), r=u>>4 (64 rows), c=u&15 (16*8 = 128 n-cols).
        {
            const __half* src = g_PT + ((size_t)b * NN + m0) * NN + n0;
            #pragma unroll
            for (int i = 0; i < 4; i++) {
                int u = t + i * 256;
                int r = u >> 4, c = u & 15;
                uint4 raw = *(const uint4*)(src + (size_t)r * NN + c * 8);
                __half2* hp = reinterpret_cast<__half2*>(&raw);
                float2 f0 = __half22float2(hp[0]);
                float2 f1 = __half22float2(hp[1]);
                float2 f2 = __half22float2(hp[2]);
                float2 f3 = __half22float2(hp[3]);
                *(float4*)(Pt + r * 132 + c * 8)     = make_float4(f0.x, f0.y, f1.x, f1.y);
                *(float4*)(Pt + r * 132 + c * 8 + 4) = make_float4(f2.x, f2.y, f3.x, f3.y);
            }
        }
        // Load V chunk [64 m][64 d], scaled by rdenom[m]
        {
            const float4* vg = (const float4*)(v + ((size_t)b * NN + m0) * DD);
            #pragma unroll
            for (int i = 0; i < 4; i++) {
                int f = t + i * 256;
                int r = f >> 4, dg = f & 15;
                float4 val = vg[f];
                float rd = g_rdenom[b * NN + m0 + r];
                val.x *= rd; val.y *= rd; val.z *= rd; val.w *= rd;
                *(float4*)(Vs + r * 68 + dg * 4) = val;
            }
        }
        __syncthreads();

        #pragma unroll 8
        for (int m = 0; m < 64; m++) {
            float4 a0 = *(float4*)(Pt + m * 132 + tx * 4);
            float4 a1 = *(float4*)(Pt + m * 132 + 64 + tx * 4);
            float4 bb = *(float4*)(Vs + m * 68 + ty * 4);
            float a[8] = {a0.x, a0.y, a0.z, a0.w, a1.x, a1.y, a1.z, a1.w};
            float bv[4] = {bb.x, bb.y, bb.z, bb.w};
            #pragma unroll
            for (int ii = 0; ii < 8; ii++)
                #pragma unroll
                for (int j = 0; j < 4; j++)
                    acc[ii][j] += a[ii] * bv[j];
        }
    }

    #pragma unroll
    for (int ii = 0; ii < 8; ii++) {
        int n = (ii < 4) ? (tx * 4 + ii) : (64 + tx * 4 + (ii - 4));
        *(float4*)(out + ((size_t)b * NN + n0 + n) * DD + ty * 4) =
            make_float4(acc[ii][0], acc[ii][1], acc[ii][2], acc[ii][3]);
    }
}

extern "C" void kernel_launch(void* const* d_in, const int* in_sizes, int n_in,
                              void* d_out, int out_size)
{
    const float* q = (const float*)d_in[0];
    const float* k = (const float*)d_in[1];
    const float* v = (const float*)d_in[2];
    const int*   mask = (const int*)d_in[3];
    float* out = (float*)d_out;

    cudaFuncSetAttribute(attn_k1, cudaFuncAttributeMaxDynamicSharedMemorySize, K1_SMEM);
    cudaFuncSetAttribute(attn_k2, cudaFuncAttributeMaxDynamicSharedMemorySize, K2_SMEM);

    attn_k1<<<dim3(16, 16), 256, K1_SMEM>>>(q, k, mask);
    attn_k2<<<dim3(16, 16), 256, K2_SMEM>>>(v, out);
}

// round 4
// speedup vs baseline: 3.1048x; 3.1048x over previous
#include <cuda_runtime.h>
#include <cuda_fp16.h>

#define BQ 16
#define NN 2048
#define DD 64
// (1/sqrt(2048)) * log2(e) — folded scale for exp2-based exp
#define CF (0.022097086912079608f * 1.4426950408889634f)

// Scratch
__device__ __half g_q16[(size_t)BQ * NN * DD];        // 4 MB  [b][n][d]
__device__ __half g_k16[(size_t)BQ * NN * DD];        // 4 MB  [b][m][d]
__device__ __half g_v16[(size_t)BQ * NN * DD];        // 4 MB  [b][m][d], scaled by rdenom
__device__ __half g_PT[(size_t)BQ * NN * NN];         // 134 MB [b][m][n]
__device__ float  g_rdenom[BQ * NN];                  // [b][m]

// exp(x/sqrt(2048)) via 2^i * poly5(f), pure FMA/ALU (no MUFU).
__device__ __forceinline__ float expp(float x, unsigned msk) {
    float xl = x * CF;
    float t  = xl + 12582912.0f;                 // round-to-nearest magic (2^23*1.5)
    int   i  = __float_as_int(t) - 0x4B400000;
    float fi = t - 12582912.0f;
    float f  = xl - fi;                          // f in [-0.5, 0.5]
    float p  = 0.0013333558f;
    p = fmaf(p, f, 0.0096181291f);
    p = fmaf(p, f, 0.0555041087f);
    p = fmaf(p, f, 0.2402265069f);
    p = fmaf(p, f, 0.6931471806f);
    p = fmaf(p, f, 1.0f);
    float r = p * __int_as_float((i + 127) << 23);
    return msk ? 0.0f : r;
}

__device__ __forceinline__ void ldsm_x4(unsigned addr, unsigned &r0, unsigned &r1,
                                        unsigned &r2, unsigned &r3) {
    asm volatile("ldmatrix.sync.aligned.m8n8.x4.shared.b16 {%0,%1,%2,%3}, [%4];\n"
                 : "=r"(r0), "=r"(r1), "=r"(r2), "=r"(r3) : "r"(addr));
}
__device__ __forceinline__ void ldsm_x4t(unsigned addr, unsigned &r0, unsigned &r1,
                                         unsigned &r2, unsigned &r3) {
    asm volatile("ldmatrix.sync.aligned.m8n8.x4.trans.shared.b16 {%0,%1,%2,%3}, [%4];\n"
                 : "=r"(r0), "=r"(r1), "=r"(r2), "=r"(r3) : "r"(addr));
}
__device__ __forceinline__ void mma16816(float *c, unsigned a0, unsigned a1, unsigned a2,
                                         unsigned a3, unsigned b0, unsigned b1) {
    asm volatile("mma.sync.aligned.m16n8k16.row.col.f32.f16.f16.f32 "
                 "{%0,%1,%2,%3}, {%4,%5,%6,%7}, {%8,%9}, {%0,%1,%2,%3};\n"
                 : "+f"(c[0]), "+f"(c[1]), "+f"(c[2]), "+f"(c[3])
                 : "r"(a0), "r"(a1), "r"(a2), "r"(a3), "r"(b0), "r"(b1));
}

// ---------- convert q,k fp32 -> fp16 ----------
__global__ void cvt_qk(const float* __restrict__ q, const float* __restrict__ k) {
    int idx = blockIdx.x * 256 + threadIdx.x;   // 524288 tasks, 4 elems each
    const float4 qv = ((const float4*)q)[idx];
    const float4 kv = ((const float4*)k)[idx];
    __half2 q0 = __floats2half2_rn(qv.x, qv.y), q1 = __floats2half2_rn(qv.z, qv.w);
    __half2 k0 = __floats2half2_rn(kv.x, kv.y), k1 = __floats2half2_rn(kv.z, kv.w);
    *(__half2*)(g_q16 + (size_t)idx * 4)     = q0;
    *(__half2*)(g_q16 + (size_t)idx * 4 + 2) = q1;
    *(__half2*)(g_k16 + (size_t)idx * 4)     = k0;
    *(__half2*)(g_k16 + (size_t)idx * 4 + 2) = k1;
}

// ---------- scale V by rdenom, fp32 -> fp16 ----------
__global__ void vscale(const float* __restrict__ v) {
    int task = blockIdx.x * 256 + threadIdx.x;  // 524288 tasks
    int row = task >> 4, c = task & 15;         // row = b*2048+m, c: 4-float group
    float4 vv = ((const float4*)v)[(size_t)row * 16 + c];
    float rd = g_rdenom[row];
    __half2 h0 = __floats2half2_rn(vv.x * rd, vv.y * rd);
    __half2 h1 = __floats2half2_rn(vv.z * rd, vv.w * rd);
    *(__half2*)(g_v16 + (size_t)row * 64 + c * 4)     = h0;
    *(__half2*)(g_v16 + (size_t)row * 64 + c * 4 + 2) = h1;
}

// ---------------- K1: S^T = K Q^T (tensor cores), mask, exp, P^T, rdenom ----------------
// Block: (m-tile 128, b). 8 warps; warp w owns m rows w*16..w*16+15, all 128 n per chunk.
#define K1_QS 0                       // half Qs[128][64] swizzled  16384
#define K1_KS 16384                   // half Ks[128][64] swizzled  16384
#define K1_MS 32768                   // uchar Ms[128 n][136]       17408
#define K1_SMEM (K1_MS + 17408)       // 50176

__global__ void __launch_bounds__(256, 2)
attn_k1(const int* __restrict__ mask)
{
    extern __shared__ char sm[];
    __half* Qs = (__half*)(sm + K1_QS);
    __half* Ks = (__half*)(sm + K1_KS);
    unsigned char* Ms = (unsigned char*)(sm + K1_MS);
    uint4* Qs4 = (uint4*)Qs;
    uint4* Ks4 = (uint4*)Ks;

    const int t = threadIdx.x, lane = t & 31, w = t >> 5;
    const int mt = blockIdx.x, b = blockIdx.y;
    const int m0 = mt * 128, wb = w * 16;
    const int lq = lane >> 2, qd = lane & 3;

    const unsigned sQ = (unsigned)__cvta_generic_to_shared(Qs);
    const unsigned sK = (unsigned)__cvta_generic_to_shared(Ks);

    // Load K tile [128 m][64 d] fp16, swizzled
    {
        const uint4* kg = (const uint4*)(g_k16 + ((size_t)(b * NN + m0)) * DD);
        #pragma unroll
        for (int i = 0; i < 4; i++) {
            int u = t + i * 256, r = u >> 3, c = u & 7;
            Ks4[r * 8 + (c ^ (r & 7))] = kg[u];
        }
    }

    float csum0 = 0.f, csum1 = 0.f;

    // ldmatrix lane roles
    const int rowA  = wb + (lane & 15);           // A (K): rows m
    const int hiA   = lane >> 4;                  // k-chunk select
    const int rowBb = (lane & 7) + ((lane >> 4) & 1) * 8;  // B (Q): n-row base
    const int hiB   = (lane >> 3) & 1;            // k-chunk select

    for (int nc = 0; nc < 16; nc++) {
        const int n0 = nc * 128;
        __syncthreads();
        // Q chunk [128 n][64 d]
        {
            const uint4* qg = (const uint4*)(g_q16 + ((size_t)(b * NN + n0)) * DD);
            #pragma unroll
            for (int i = 0; i < 4; i++) {
                int u = t + i * 256, r = u >> 3, c = u & 7;
                Qs4[r * 8 + (c ^ (r & 7))] = qg[u];
            }
        }
        // mask tile [128 n][128 m] int32 -> flag bytes
        {
            const int* mg = mask + ((size_t)(b * NN + n0)) * NN + m0;
            #pragma unroll
            for (int i = 0; i < 16; i++) {
                int u = t + i * 256, n = u >> 5, c = u & 31;
                int4 mv = *(const int4*)(mg + (size_t)n * NN + c * 4);
                unsigned pw = (mv.x ? 0x1u : 0u) | (mv.y ? 0x100u : 0u) |
                              (mv.z ? 0x10000u : 0u) | (mv.w ? 0x1000000u : 0u);
                ((unsigned*)(Ms + n * 136))[c] = pw;
            }
        }
        __syncthreads();

        float acc[16][4];
        #pragma unroll
        for (int i = 0; i < 16; i++)
            #pragma unroll
            for (int j = 0; j < 4; j++) acc[i][j] = 0.f;

        #pragma unroll
        for (int s = 0; s < 4; s++) {
            unsigned a0, a1, a2, a3;
            unsigned aaddr = sK + rowA * 128 + ((((s << 1) | hiA) ^ (rowA & 7)) << 4);
            ldsm_x4(aaddr, a0, a1, a2, a3);
            #pragma unroll
            for (int nt2 = 0; nt2 < 8; nt2++) {
                int rowB = nt2 * 16 + rowBb;
                unsigned b0, b1, b2, b3;
                unsigned baddr = sQ + rowB * 128 + ((((s << 1) | hiB) ^ (rowB & 7)) << 4);
                ldsm_x4(baddr, b0, b1, b2, b3);
                mma16816(acc[nt2 * 2],     a0, a1, a2, a3, b0, b1);
                mma16816(acc[nt2 * 2 + 1], a0, a1, a2, a3, b2, b3);
            }
        }

        // epilogue: mask, exp, col-sums, P^T store
        const int ml = wb + lq;  // local m row (this thread's first row)
        __half* prow = g_PT + ((size_t)(b * NN + m0 + ml)) * NN + n0 + 2 * qd;
        #pragma unroll
        for (int tile = 0; tile < 16; tile++) {
            int ncol = tile * 8 + 2 * qd;
            unsigned mka = Ms[ncol * 136 + ml];
            unsigned mkb = Ms[(ncol + 1) * 136 + ml];
            unsigned mkc = Ms[ncol * 136 + ml + 8];
            unsigned mkd = Ms[(ncol + 1) * 136 + ml + 8];
            float p0 = expp(acc[tile][0], mka);
            float p1 = expp(acc[tile][1], mkb);
            float p2 = expp(acc[tile][2], mkc);
            float p3 = expp(acc[tile][3], mkd);
            csum0 += p0 + p1;
            csum1 += p2 + p3;
            *(__half2*)(prow + tile * 8)            = __floats2half2_rn(p0, p1);
            *(__half2*)(prow + 8 * NN + tile * 8)   = __floats2half2_rn(p2, p3);
        }
    }

    // reduce column sums over the 4 lanes sharing each m-row
    csum0 += __shfl_xor_sync(0xFFFFFFFFu, csum0, 1);
    csum0 += __shfl_xor_sync(0xFFFFFFFFu, csum0, 2);
    csum1 += __shfl_xor_sync(0xFFFFFFFFu, csum1, 1);
    csum1 += __shfl_xor_sync(0xFFFFFFFFu, csum1, 2);
    if (qd == 0) {
        g_rdenom[b * NN + m0 + wb + lq]     = 1.0f / csum0;
        g_rdenom[b * NN + m0 + wb + lq + 8] = 1.0f / csum1;
    }
}

// ---------------- K2: out = P^T^T @ Vr (tensor cores) ----------------
// Block: (n-tile 128, b). Warp w owns n rows w*16..+15, all 64 d.
#define K2_PT 0                       // half PTs[128 m][128 n] swizzled  32768
#define K2_VS 32768                   // half Vs[128 m][64 d]  swizzled  16384
#define K2_SMEM (K2_VS + 16384)       // 49152

__global__ void __launch_bounds__(256, 2)
attn_k2(float* __restrict__ out)
{
    extern __shared__ char sm[];
    __half* PTs = (__half*)(sm + K2_PT);
    __half* Vs  = (__half*)(sm + K2_VS);
    uint4* PTs4 = (uint4*)PTs;
    uint4* Vs4  = (uint4*)Vs;

    const int t = threadIdx.x, lane = t & 31, w = t >> 5;
    const int nt = blockIdx.x, b = blockIdx.y;
    const int n0 = nt * 128, wb = w * 16;
    const int lq = lane >> 2, qd = lane & 3;

    const unsigned sP = (unsigned)__cvta_generic_to_shared(PTs);
    const unsigned sV = (unsigned)__cvta_generic_to_shared(Vs);

    float acc[8][4];
    #pragma unroll
    for (int i = 0; i < 8; i++)
        #pragma unroll
        for (int j = 0; j < 4; j++) acc[i][j] = 0.f;

    // lane roles (trans ldmatrix)
    const int mA  = (lane & 7) + ((lane >> 4) & 1) * 8;  // A: m row base
    const int cAh = (lane >> 3) & 1;                      // n-chunk select
    const int mB  = (lane & 7) + ((lane >> 3) & 1) * 8;  // B: m row base
    const int cBh = (lane >> 4) & 1;                      // d-chunk select
    const int cA0 = (wb >> 3);

    for (int mc = 0; mc < 16; mc++) {
        __syncthreads();
        // P^T tile [128 m][128 n]
        {
            const uint4* pg = (const uint4*)(g_PT + ((size_t)(b * NN + mc * 128)) * NN + n0);
            #pragma unroll
            for (int i = 0; i < 8; i++) {
                int u = t + i * 256, r = u >> 4, c = u & 15;
                PTs4[r * 16 + (c ^ (r & 7))] = pg[(size_t)r * 256 + c];
            }
        }
        // V tile [128 m][64 d] (pre-scaled fp16)
        {
            const uint4* vg = (const uint4*)(g_v16 + ((size_t)(b * NN + mc * 128)) * DD);
            #pragma unroll
            for (int i = 0; i < 4; i++) {
                int u = t + i * 256, r = u >> 3, c = u & 7;
                Vs4[r * 8 + (c ^ (r & 7))] = vg[u];
            }
        }
        __syncthreads();

        #pragma unroll
        for (int ks = 0; ks < 8; ks++) {
            int mrA = ks * 16 + mA;
            unsigned a0, a1, a2, a3;
            unsigned aaddr = sP + mrA * 256 + (((cA0 + cAh) ^ (mrA & 7)) << 4);
            ldsm_x4t(aaddr, a0, a1, a2, a3);
            int mrB = ks * 16 + mB;
            #pragma unroll
            for (int dt2 = 0; dt2 < 4; dt2++) {
                unsigned b0, b1, b2, b3;
                unsigned baddr = sV + mrB * 128 + (((dt2 * 2 + cBh) ^ (mrB & 7)) << 4);
                ldsm_x4t(baddr, b0, b1, b2, b3);
                mma16816(acc[dt2 * 2],     a0, a1, a2, a3, b0, b1);
                mma16816(acc[dt2 * 2 + 1], a0, a1, a2, a3, b2, b3);
            }
        }
    }

    // store out [n][d] fp32
    float* orow = out + ((size_t)(b * NN + n0 + wb + lq)) * DD + 2 * qd;
    #pragma unroll
    for (int dt = 0; dt < 8; dt++) {
        *(float2*)(orow + dt * 8)           = make_float2(acc[dt][0], acc[dt][1]);
        *(float2*)(orow + 8 * DD + dt * 8)  = make_float2(acc[dt][2], acc[dt][3]);
    }
}

extern "C" void kernel_launch(void* const* d_in, const int* in_sizes, int n_in,
                              void* d_out, int out_size)
{
    const float* q = (const float*)d_in[0];
    const float* k = (const float*)d_in[1];
    const float* v = (const float*)d_in[2];
    const int* mask = (const int*)d_in[3];
    float* out = (float*)d_out;

    cudaFuncSetAttribute(attn_k1, cudaFuncAttributeMaxDynamicSharedMemorySize, K1_SMEM);
    cudaFuncSetAttribute(attn_k2, cudaFuncAttributeMaxDynamicSharedMemorySize, K2_SMEM);

    cvt_qk<<<2048, 256>>>(q, k);
    attn_k1<<<dim3(16, 16), 256, K1_SMEM>>>(mask);
    vscale<<<2048, 256>>>(v);
    attn_k2<<<dim3(16, 16), 256, K2_SMEM>>>(out);
}